// round 2
// baseline (speedup 1.0000x reference)
#include <cuda_runtime.h>
#include <cstddef>

// Problem constants (fixed by setup_inputs)
#define BB 2
#define DD 48
#define HH 320
#define WW 640
#define RR 2
#define KK 5
#define K2 25
#define HW (HH * WW)

// Tiling
#define TH 8
#define TW 32
#define DC 16
#define PH (TH + 2 * RR)   // 12
#define PW (TW + 2 * RR)   // 36
#define PD (DC + 2)        // 18
#define NTHREADS 256

// Intermediate buffer for pass-1 result (allocation-free scratch)
__device__ float g_y[(size_t)BB * DD * HH * WW];

__global__ void __launch_bounds__(NTHREADS, 2)
lga_kernel(const float* __restrict__ xin,
           const float* __restrict__ wts,
           float* __restrict__ xout)
{
    __shared__ float xs[PD][PH][PW];   // 18*12*36*4 = 31104 B

    const int t  = threadIdx.x;
    const int tx = t & 31;       // 0..31  (W within tile)
    const int ty = t >> 5;       // 0..7   (H within tile)

    const int w0p = blockIdx.x * TW;
    const int h0  = blockIdx.y * TH;
    const int b   = blockIdx.z;

    const int gh = h0 + ty;
    const int gw = w0p + tx;

    // weight base: wts[b, c, gh, gw], channel stride = HW
    const float* wbase = wts + ((size_t)b * (3 * K2) * HH + gh) * WW + gw;

    for (int chunk = 0; chunk < DD / DC; ++chunk) {
        const int d0 = chunk * DC;

        __syncthreads();   // protect xs from previous chunk's readers

        // ---- fill shared x slab: planes d0-1 .. d0+DC, spatial halo r=2 ----
        #pragma unroll 4
        for (int idx = t; idx < PD * PH * PW; idx += NTHREADS) {
            const int plane = idx / (PH * PW);
            const int rem   = idx - plane * (PH * PW);
            const int row   = rem / PW;
            const int col   = rem - row * PW;
            const int gd = d0 - 1 + plane;
            const int hh = h0 + row - RR;
            const int ww = w0p + col - RR;
            float v = 0.0f;
            if ((unsigned)gd < DD && (unsigned)hh < HH && (unsigned)ww < WW)
                v = xin[(((size_t)b * DD + gd) * HH + hh) * WW + ww];
            xs[plane][row][col] = v;
        }
        __syncthreads();

        // ---- compute DC disparities for this pixel ----
        float acc[DC];
        #pragma unroll
        for (int dd = 0; dd < DC; ++dd) acc[dd] = 0.0f;

        #pragma unroll 1
        for (int ij = 0; ij < K2; ++ij) {
            const int i = ij / KK;
            const int j = ij - i * KK;

            const float wt0 = __ldg(wbase + (size_t)ij * HW);
            const float wt1 = __ldg(wbase + (size_t)(K2 + ij) * HW);
            const float wt2 = __ldg(wbase + (size_t)(2 * K2 + ij) * HW);

            // disparity column at spatial tap (ty+i, tx+j)
            float colv[PD];
            #pragma unroll
            for (int p = 0; p < PD; ++p)
                colv[p] = xs[p][ty + i][tx + j];

            #pragma unroll
            for (int dd = 0; dd < DC; ++dd) {
                acc[dd] = fmaf(wt0, colv[dd + 1], acc[dd]);  // x[d]
                acc[dd] = fmaf(wt1, colv[dd],     acc[dd]);  // x[d-1]
                acc[dd] = fmaf(wt2, colv[dd + 2], acc[dd]);  // x[d+1]
            }
        }

        // ---- write out (coalesced along tx) ----
        #pragma unroll
        for (int dd = 0; dd < DC; ++dd)
            xout[(((size_t)b * DD + (d0 + dd)) * HH + gh) * WW + gw] = acc[dd];
    }
}

extern "C" void kernel_launch(void* const* d_in, const int* in_sizes, int n_in,
                              void* d_out, int out_size)
{
    const float* x = (const float*)d_in[0];   // [B, D, H, W]
    const float* w = (const float*)d_in[1];   // [B, 75, H, W]
    // d_in[2] = radius (fixed at 2, baked into constants)
    float* out = (float*)d_out;

    float* ybuf = nullptr;
    cudaGetSymbolAddress((void**)&ybuf, g_y);

    dim3 grid(WW / TW, HH / TH, BB);   // 20 x 40 x 2
    lga_kernel<<<grid, NTHREADS>>>(x, w, ybuf);   // pass 1: y = LGA(x, w)
    lga_kernel<<<grid, NTHREADS>>>(ybuf, w, out); // pass 2: out = LGA(y, w)
}

// round 3
// speedup vs baseline: 2.6033x; 2.6033x over previous
#include <cuda_runtime.h>
#include <cstddef>

// Problem constants (fixed by setup_inputs)
#define BB 2
#define DD 48
#define HH 320
#define WW 640
#define RR 2
#define KK 5
#define K2 25
#define HW (HH * WW)

// Tiling
#define TH 8
#define TW 32
#define DC 16
#define PH (TH + 2 * RR)   // 12
#define PW (TW + 2 * RR)   // 36
#define PD (DC + 2)        // 18
#define PDP 20             // padded plane stride (floats); 80B -> conflict-free LDS.128
#define NT 256

// Intermediate buffer for pass-1 result (allocation-free scratch)
__device__ float g_y[(size_t)BB * DD * HH * WW];

__device__ __forceinline__ unsigned long long pk2(float lo, float hi) {
    unsigned long long r;
    asm("mov.b64 %0, {%1, %2};" : "=l"(r) : "f"(lo), "f"(hi));
    return r;
}
__device__ __forceinline__ void ffma2(unsigned long long &acc,
                                      unsigned long long a,
                                      unsigned long long b) {
    asm("fma.rn.f32x2 %0, %1, %2, %0;" : "+l"(acc) : "l"(a), "l"(b));
}
__device__ __forceinline__ void upk2(unsigned long long v, float &lo, float &hi) {
    asm("mov.b64 {%0, %1}, %2;" : "=f"(lo), "=f"(hi) : "l"(v));
}

union Q4 { float4 f; unsigned long long u[2]; };
union Q2 { float2 f; unsigned long long u; };

__global__ void __launch_bounds__(NT, 3)
lga_kernel(const float* __restrict__ xin,
           const float* __restrict__ wts,
           float* __restrict__ xout)
{
    __shared__ float xs[PH * PW * PDP];   // 12*36*20*4 = 34560 B

    const int t  = threadIdx.x;
    const int tx = t & 31;       // W within tile
    const int ty = t >> 5;       // H within tile

    const int w0p = blockIdx.x * TW;
    const int h0  = blockIdx.y * TH;
    const int b   = blockIdx.z;

    const int gh = h0 + ty;
    const int gw = w0p + tx;

    // weight base: wts[b, c, gh, gw], channel stride = HW
    const float* wb = wts + ((size_t)b * (3 * K2)) * HW + (size_t)gh * WW + gw;

    for (int chunk = 0; chunk < DD / DC; ++chunk) {
        const int d0 = chunk * DC;

        __syncthreads();   // protect xs from previous chunk's readers

        // ---- fill shared slab, plane-contiguous: xs[(row*PW+col)*PDP + p] ----
        // Each thread owns whole (row,col) columns -> one STS.128 per 4 planes,
        // conflict-free (80B lane stride covers all 32 banks per phase).
        for (int pos = t; pos < PH * PW; pos += NT) {
            const int row = pos / PW;
            const int col = pos - row * PW;
            const int hh = h0 + row - RR;
            const int ww = w0p + col - RR;
            const bool sok = ((unsigned)hh < HH) & ((unsigned)ww < WW);
            const float* src = xin + ((size_t)b * DD * HH + hh) * (size_t)WW + ww;

            float buf[PDP];
            #pragma unroll
            for (int p = 0; p < PD; ++p) {
                const int gd = d0 - 1 + p;
                float v = 0.0f;
                if (sok && (unsigned)gd < DD) v = __ldg(src + (size_t)gd * HW);
                buf[p] = v;
            }
            buf[PD] = 0.0f; buf[PD + 1] = 0.0f;

            float4* dst = (float4*)&xs[pos * PDP];
            #pragma unroll
            for (int q = 0; q < PDP / 4; ++q)
                dst[q] = make_float4(buf[4*q], buf[4*q+1], buf[4*q+2], buf[4*q+3]);
        }
        __syncthreads();

        // ---- compute DC disparities (as DC/2 packed f32x2 pairs) ----
        unsigned long long acc[DC / 2];
        #pragma unroll
        for (int k = 0; k < DC / 2; ++k) acc[k] = 0ull;

        #pragma unroll
        for (int i = 0; i < KK; ++i) {
            #pragma unroll
            for (int j = 0; j < KK; ++j) {
                const int ij = i * KK + j;

                const float wt0 = __ldg(wb + (size_t)ij * HW);
                const float wt1 = __ldg(wb + (size_t)(K2 + ij) * HW);
                const float wt2 = __ldg(wb + (size_t)(2 * K2 + ij) * HW);
                const unsigned long long W0 = pk2(wt0, wt0);
                const unsigned long long W1 = pk2(wt1, wt1);
                const unsigned long long W2 = pk2(wt2, wt2);

                // disparity column at spatial tap (ty+i, tx+j): compile-time offsets
                const float* cb = &xs[((ty + i) * PW + (tx + j)) * PDP];
                Q4 a0, a1, a2, a3; Q2 a4;
                a0.f = *(const float4*)(cb + 0);
                a1.f = *(const float4*)(cb + 4);
                a2.f = *(const float4*)(cb + 8);
                a3.f = *(const float4*)(cb + 12);
                a4.f = *(const float2*)(cb + 16);

                // even-aligned pairs come free out of LDS.128 register quads
                const unsigned long long E[9] = {
                    a0.u[0], a0.u[1], a1.u[0], a1.u[1],
                    a2.u[0], a2.u[1], a3.u[0], a3.u[1], a4.u
                };
                const float c[PD] = {
                    a0.f.x, a0.f.y, a0.f.z, a0.f.w,
                    a1.f.x, a1.f.y, a1.f.z, a1.f.w,
                    a2.f.x, a2.f.y, a2.f.z, a2.f.w,
                    a3.f.x, a3.f.y, a3.f.z, a3.f.w,
                    a4.f.x, a4.f.y
                };

                #pragma unroll
                for (int k = 0; k < DC / 2; ++k) {
                    // acc pair covers d = d0+2k, d0+2k+1 ; colv[p] = x[d0-1+p]
                    ffma2(acc[k], W1, E[k]);                          // x[d-1]
                    ffma2(acc[k], W0, pk2(c[2*k + 1], c[2*k + 2]));   // x[d]
                    ffma2(acc[k], W2, E[k + 1]);                      // x[d+1]
                }
            }
        }

        // ---- write out (coalesced along tx) ----
        float* outp = xout + (((size_t)b * DD + d0) * HH + gh) * (size_t)WW + gw;
        #pragma unroll
        for (int k = 0; k < DC / 2; ++k) {
            float lo, hi;
            upk2(acc[k], lo, hi);
            outp[(size_t)(2 * k) * HW]     = lo;
            outp[(size_t)(2 * k + 1) * HW] = hi;
        }
    }
}

extern "C" void kernel_launch(void* const* d_in, const int* in_sizes, int n_in,
                              void* d_out, int out_size)
{
    const float* x = (const float*)d_in[0];   // [B, D, H, W]
    const float* w = (const float*)d_in[1];   // [B, 75, H, W]
    // d_in[2] = radius (fixed at 2, baked into constants)
    float* out = (float*)d_out;

    float* ybuf = nullptr;
    cudaGetSymbolAddress((void**)&ybuf, g_y);

    dim3 grid(WW / TW, HH / TH, BB);   // 20 x 40 x 2
    lga_kernel<<<grid, NT>>>(x, w, ybuf);   // pass 1: y = LGA(x, w)
    lga_kernel<<<grid, NT>>>(ybuf, w, out); // pass 2: out = LGA(y, w)
}

// round 4
// speedup vs baseline: 2.6803x; 1.0296x over previous
#include <cuda_runtime.h>
#include <cstddef>

// Problem constants (fixed by setup_inputs)
#define BB 2
#define DD 48
#define HH 320
#define WW 640
#define RR 2
#define KK 5
#define K2 25
#define HW (HH * WW)

// Tiling: 16x32 output tile, 256 threads, each thread owns 2 vertical pixels
#define TH 16
#define TW 32
#define DC 16
#define PH (TH + 2 * RR)   // 20
#define PW (TW + 2 * RR)   // 36
#define PD (DC + 2)        // 18 planes used
#define PDP 20             // padded plane stride (80B -> conflict-free LDS.128)
#define NT 256
#define SMEM_BYTES (PH * PW * PDP * 4)   // 57600

// Intermediate buffer for pass-1 result (allocation-free scratch)
__device__ float g_y[(size_t)BB * DD * HH * WW];

__device__ __forceinline__ unsigned long long pk2(float lo, float hi) {
    unsigned long long r;
    asm("mov.b64 %0, {%1, %2};" : "=l"(r) : "f"(lo), "f"(hi));
    return r;
}
__device__ __forceinline__ void ffma2(unsigned long long &acc,
                                      unsigned long long a,
                                      unsigned long long b) {
    asm("fma.rn.f32x2 %0, %1, %2, %0;" : "+l"(acc) : "l"(a), "l"(b));
}
__device__ __forceinline__ void upk2(unsigned long long v, float &lo, float &hi) {
    asm("mov.b64 {%0, %1}, %2;" : "=f"(lo), "=f"(hi) : "l"(v));
}

union Q4 { float4 f; unsigned long long u[2]; };
union Q2 { float2 f; unsigned long long u; };

__global__ void __launch_bounds__(NT, 2)
lga_kernel(const float* __restrict__ xin,
           const float* __restrict__ wts,
           float* __restrict__ xout)
{
    extern __shared__ float xs[];   // [PH][PW][PDP]

    const int t  = threadIdx.x;
    const int tx = t & 31;       // W within tile
    const int ty = t >> 5;       // 0..7 -> output rows 2ty, 2ty+1

    const int w0p = blockIdx.x * TW;
    const int h0  = blockIdx.y * TH;
    const int b   = blockIdx.z;

    const int gh0 = h0 + 2 * ty;
    const int gw  = w0p + tx;

    // weight base: wts[b, c, gh, gw], channel stride = HW
    const float* wb0 = wts + ((size_t)b * (3 * K2)) * HW + (size_t)gh0 * WW + gw;
    const float* wb1 = wb0 + WW;   // row gh0+1

    #pragma unroll 1
    for (int chunk = 0; chunk < DD / DC; ++chunk) {
        const int d0 = chunk * DC;

        __syncthreads();   // protect xs from previous chunk's readers

        // ---- fill shared slab, plane-contiguous: xs[(row*PW+col)*PDP + p] ----
        for (int pos = t; pos < PH * PW; pos += NT) {
            const int row = pos / PW;
            const int col = pos - row * PW;
            const int hh = h0 + row - RR;
            const int ww = w0p + col - RR;
            const bool sok = ((unsigned)hh < HH) & ((unsigned)ww < WW);
            const float* src = xin + ((size_t)b * DD * HH + hh) * (size_t)WW + ww;

            float buf[PDP];
            #pragma unroll
            for (int p = 0; p < PD; ++p) {
                const int gd = d0 - 1 + p;
                float v = 0.0f;
                if (sok && (unsigned)gd < DD) v = __ldg(src + (size_t)gd * HW);
                buf[p] = v;
            }
            buf[PD] = 0.0f; buf[PD + 1] = 0.0f;

            float4* dst = (float4*)&xs[pos * PDP];
            #pragma unroll
            for (int q = 0; q < PDP / 4; ++q)
                dst[q] = make_float4(buf[4*q], buf[4*q+1], buf[4*q+2], buf[4*q+3]);
        }
        __syncthreads();

        // ---- two vertically adjacent pixels per thread ----
        unsigned long long acc0[DC / 2], acc1[DC / 2];
        #pragma unroll
        for (int k = 0; k < DC / 2; ++k) { acc0[k] = 0ull; acc1[k] = 0ull; }

        // slab row for pixel0 tap (i,j) is 2ty + i ; pixel1 tap (i,j) is 2ty+1+i.
        // Union over both pixels: slab rows 2ty + i for i = 0..5.
        #pragma unroll
        for (int i = 0; i < KK + 1; ++i) {
            #pragma unroll
            for (int j = 0; j < KK; ++j) {
                // column at slab (2ty+i, tx+j): compile-time offsets, lane stride 80B
                const float* cb = &xs[((2 * ty + i) * PW + (tx + j)) * PDP];
                Q4 a0, a1, a2, a3; Q2 a4;
                a0.f = *(const float4*)(cb + 0);
                a1.f = *(const float4*)(cb + 4);
                a2.f = *(const float4*)(cb + 8);
                a3.f = *(const float4*)(cb + 12);
                a4.f = *(const float2*)(cb + 16);

                const unsigned long long E[9] = {
                    a0.u[0], a0.u[1], a1.u[0], a1.u[1],
                    a2.u[0], a2.u[1], a3.u[0], a3.u[1], a4.u
                };
                const float c[PD] = {
                    a0.f.x, a0.f.y, a0.f.z, a0.f.w,
                    a1.f.x, a1.f.y, a1.f.z, a1.f.w,
                    a2.f.x, a2.f.y, a2.f.z, a2.f.w,
                    a3.f.x, a3.f.y, a3.f.z, a3.f.w,
                    a4.f.x, a4.f.y
                };
                // odd-aligned pairs, shared by both pixels
                unsigned long long O[DC / 2];
                #pragma unroll
                for (int k = 0; k < DC / 2; ++k)
                    O[k] = pk2(c[2 * k + 1], c[2 * k + 2]);

                if (i < KK) {                       // pixel0 tap (i, j)
                    const int ij = i * KK + j;
                    const float wt0 = __ldg(wb0 + (size_t)ij * HW);
                    const float wt1 = __ldg(wb0 + (size_t)(K2 + ij) * HW);
                    const float wt2 = __ldg(wb0 + (size_t)(2 * K2 + ij) * HW);
                    const unsigned long long W0 = pk2(wt0, wt0);
                    const unsigned long long W1 = pk2(wt1, wt1);
                    const unsigned long long W2 = pk2(wt2, wt2);
                    #pragma unroll
                    for (int k = 0; k < DC / 2; ++k) {
                        ffma2(acc0[k], W1, E[k]);       // x[d-1]
                        ffma2(acc0[k], W0, O[k]);       // x[d]
                        ffma2(acc0[k], W2, E[k + 1]);   // x[d+1]
                    }
                }
                if (i >= 1) {                       // pixel1 tap (i-1, j)
                    const int ij = (i - 1) * KK + j;
                    const float wt0 = __ldg(wb1 + (size_t)ij * HW);
                    const float wt1 = __ldg(wb1 + (size_t)(K2 + ij) * HW);
                    const float wt2 = __ldg(wb1 + (size_t)(2 * K2 + ij) * HW);
                    const unsigned long long W0 = pk2(wt0, wt0);
                    const unsigned long long W1 = pk2(wt1, wt1);
                    const unsigned long long W2 = pk2(wt2, wt2);
                    #pragma unroll
                    for (int k = 0; k < DC / 2; ++k) {
                        ffma2(acc1[k], W1, E[k]);
                        ffma2(acc1[k], W0, O[k]);
                        ffma2(acc1[k], W2, E[k + 1]);
                    }
                }
            }
        }

        // ---- write out (coalesced along tx) ----
        float* outp0 = xout + (((size_t)b * DD + d0) * HH + gh0) * (size_t)WW + gw;
        float* outp1 = outp0 + WW;
        #pragma unroll
        for (int k = 0; k < DC / 2; ++k) {
            float lo, hi;
            upk2(acc0[k], lo, hi);
            outp0[(size_t)(2 * k) * HW]     = lo;
            outp0[(size_t)(2 * k + 1) * HW] = hi;
            upk2(acc1[k], lo, hi);
            outp1[(size_t)(2 * k) * HW]     = lo;
            outp1[(size_t)(2 * k + 1) * HW] = hi;
        }
    }
}

extern "C" void kernel_launch(void* const* d_in, const int* in_sizes, int n_in,
                              void* d_out, int out_size)
{
    const float* x = (const float*)d_in[0];   // [B, D, H, W]
    const float* w = (const float*)d_in[1];   // [B, 75, H, W]
    float* out = (float*)d_out;

    float* ybuf = nullptr;
    cudaGetSymbolAddress((void**)&ybuf, g_y);

    cudaFuncSetAttribute(lga_kernel,
                         cudaFuncAttributeMaxDynamicSharedMemorySize, SMEM_BYTES);

    dim3 grid(WW / TW, HH / TH, BB);   // 20 x 20 x 2
    lga_kernel<<<grid, NT, SMEM_BYTES>>>(x, w, ybuf);   // pass 1
    lga_kernel<<<grid, NT, SMEM_BYTES>>>(ybuf, w, out); // pass 2
}

// round 5
// speedup vs baseline: 2.7069x; 1.0100x over previous
#include <cuda_runtime.h>
#include <cstddef>

// Problem constants (fixed by setup_inputs)
#define BB 2
#define DD 48
#define HH 320
#define WW 640
#define RR 2
#define KK 5
#define K2 25
#define HW (HH * WW)

// Tiling: 16x32 output tile, 256 threads, 2 vertical pixels per thread
#define TH 16
#define TW 32
#define DC 24              // disparities per chunk (2 chunks)
#define PH (TH + 2 * RR)   // 20
#define PW (TW + 2 * RR)   // 36
#define PD (DC + 2)        // 26 planes used
#define PDP 28             // plane stride (112B -> conflict-free LDS.128)
#define NT 256
#define SMEM_BYTES (PH * PW * PDP * 4)   // 80640

// Intermediate buffer for pass-1 result (allocation-free scratch)
__device__ float g_y[(size_t)BB * DD * HH * WW];

__device__ __forceinline__ unsigned long long pk2(float lo, float hi) {
    unsigned long long r;
    asm("mov.b64 %0, {%1, %2};" : "=l"(r) : "f"(lo), "f"(hi));
    return r;
}
__device__ __forceinline__ void ffma2(unsigned long long &acc,
                                      unsigned long long a,
                                      unsigned long long b) {
    asm("fma.rn.f32x2 %0, %1, %2, %0;" : "+l"(acc) : "l"(a), "l"(b));
}
__device__ __forceinline__ void upk2(unsigned long long v, float &lo, float &hi) {
    asm("mov.b64 {%0, %1}, %2;" : "=f"(lo), "=f"(hi) : "l"(v));
}

union Q4 { float4 f; unsigned long long u[2]; };
union Q2 { float2 f; unsigned long long u; };

__global__ void __launch_bounds__(NT, 2)
lga_kernel(const float* __restrict__ xin,
           const float* __restrict__ wts,
           float* __restrict__ xout)
{
    extern __shared__ float xs[];   // [PH][PW][PDP]

    const int t  = threadIdx.x;
    const int tx = t & 31;       // W within tile
    const int ty = t >> 5;       // 0..7 -> output rows 2ty, 2ty+1

    const int w0p = blockIdx.x * TW;
    const int h0  = blockIdx.y * TH;
    const int b   = blockIdx.z;

    const int gh0 = h0 + 2 * ty;
    const int gw  = w0p + tx;

    // weight base: wts[b, c, gh, gw], channel stride = HW
    const float* wb0 = wts + ((size_t)b * (3 * K2)) * HW + (size_t)gh0 * WW + gw;
    const float* wb1 = wb0 + WW;   // row gh0+1

    #pragma unroll 1
    for (int chunk = 0; chunk < DD / DC; ++chunk) {
        const int d0 = chunk * DC;

        __syncthreads();   // protect xs from previous chunk's readers

        // ---- fill shared slab, plane-contiguous: xs[(row*PW+col)*PDP + p] ----
        for (int pos = t; pos < PH * PW; pos += NT) {
            const int row = pos / PW;
            const int col = pos - row * PW;
            const int hh = h0 + row - RR;
            const int ww = w0p + col - RR;
            const bool sok = ((unsigned)hh < HH) & ((unsigned)ww < WW);
            const float* src = xin + ((size_t)b * DD * HH + hh) * (size_t)WW + ww;

            float buf[PDP];
            #pragma unroll
            for (int p = 0; p < PD; ++p) {
                const int gd = d0 - 1 + p;
                float v = 0.0f;
                if (sok && (unsigned)gd < DD) v = __ldg(src + (size_t)gd * HW);
                buf[p] = v;
            }
            buf[PD] = 0.0f; buf[PD + 1] = 0.0f;

            float4* dst = (float4*)&xs[pos * PDP];
            #pragma unroll
            for (int q = 0; q < PDP / 4; ++q)
                dst[q] = make_float4(buf[4*q], buf[4*q+1], buf[4*q+2], buf[4*q+3]);
        }
        __syncthreads();

        // ---- two vertically adjacent pixels per thread ----
        unsigned long long acc0[DC / 2], acc1[DC / 2];
        #pragma unroll
        for (int k = 0; k < DC / 2; ++k) { acc0[k] = 0ull; acc1[k] = 0ull; }

        // slab row for pixel0 tap (i,j): 2ty+i ; pixel1 tap (i,j): 2ty+1+i.
        // Union over both pixels: slab rows 2ty + i, i = 0..5.
        #pragma unroll
        for (int i = 0; i < KK + 1; ++i) {
            // per-(row,group) pointers: inner offsets j*HW fold into LDG immediates
            const float* p0a = wb0 + (size_t)(0 * K2 + i * KK) * HW;
            const float* p1a = wb0 + (size_t)(1 * K2 + i * KK) * HW;
            const float* p2a = wb0 + (size_t)(2 * K2 + i * KK) * HW;
            const float* p0b = wb1 + (size_t)(0 * K2 + (i - 1) * KK) * HW;
            const float* p1b = wb1 + (size_t)(1 * K2 + (i - 1) * KK) * HW;
            const float* p2b = wb1 + (size_t)(2 * K2 + (i - 1) * KK) * HW;

            #pragma unroll
            for (int j = 0; j < KK; ++j) {
                // disparity column at slab (2ty+i, tx+j); 112B lane stride
                const float* cb = &xs[((2 * ty + i) * PW + (tx + j)) * PDP];
                Q4 a0, a1, a2, a3, a4, a5; Q2 a6;
                a0.f = *(const float4*)(cb + 0);
                a1.f = *(const float4*)(cb + 4);
                a2.f = *(const float4*)(cb + 8);
                a3.f = *(const float4*)(cb + 12);
                a4.f = *(const float4*)(cb + 16);
                a5.f = *(const float4*)(cb + 20);
                a6.f = *(const float2*)(cb + 24);

                const unsigned long long E[13] = {
                    a0.u[0], a0.u[1], a1.u[0], a1.u[1],
                    a2.u[0], a2.u[1], a3.u[0], a3.u[1],
                    a4.u[0], a4.u[1], a5.u[0], a5.u[1], a6.u
                };
                const float c[PD] = {
                    a0.f.x, a0.f.y, a0.f.z, a0.f.w,
                    a1.f.x, a1.f.y, a1.f.z, a1.f.w,
                    a2.f.x, a2.f.y, a2.f.z, a2.f.w,
                    a3.f.x, a3.f.y, a3.f.z, a3.f.w,
                    a4.f.x, a4.f.y, a4.f.z, a4.f.w,
                    a5.f.x, a5.f.y, a5.f.z, a5.f.w,
                    a6.f.x, a6.f.y
                };

                unsigned long long W0a = 0, W1a = 0, W2a = 0;
                unsigned long long W0b = 0, W1b = 0, W2b = 0;
                if (i < KK) {            // pixel0 tap (i, j)
                    const float wt0 = __ldg(p0a + (size_t)j * HW);
                    const float wt1 = __ldg(p1a + (size_t)j * HW);
                    const float wt2 = __ldg(p2a + (size_t)j * HW);
                    W0a = pk2(wt0, wt0); W1a = pk2(wt1, wt1); W2a = pk2(wt2, wt2);
                }
                if (i >= 1) {            // pixel1 tap (i-1, j)
                    const float wt0 = __ldg(p0b + (size_t)j * HW);
                    const float wt1 = __ldg(p1b + (size_t)j * HW);
                    const float wt2 = __ldg(p2b + (size_t)j * HW);
                    W0b = pk2(wt0, wt0); W1b = pk2(wt1, wt1); W2b = pk2(wt2, wt2);
                }

                #pragma unroll
                for (int k = 0; k < DC / 2; ++k) {
                    // acc pair covers d = d0+2k, d0+2k+1 ; c[p] = x[d0-1+p]
                    const unsigned long long O = pk2(c[2*k + 1], c[2*k + 2]);
                    if (i < KK) {
                        ffma2(acc0[k], W1a, E[k]);       // x[d-1]
                        ffma2(acc0[k], W0a, O);          // x[d]
                        ffma2(acc0[k], W2a, E[k + 1]);   // x[d+1]
                    }
                    if (i >= 1) {
                        ffma2(acc1[k], W1b, E[k]);
                        ffma2(acc1[k], W0b, O);
                        ffma2(acc1[k], W2b, E[k + 1]);
                    }
                }
            }
        }

        // ---- write out (coalesced along tx) ----
        float* outp0 = xout + (((size_t)b * DD + d0) * HH + gh0) * (size_t)WW + gw;
        float* outp1 = outp0 + WW;
        #pragma unroll
        for (int k = 0; k < DC / 2; ++k) {
            float lo, hi;
            upk2(acc0[k], lo, hi);
            outp0[(size_t)(2 * k) * HW]     = lo;
            outp0[(size_t)(2 * k + 1) * HW] = hi;
            upk2(acc1[k], lo, hi);
            outp1[(size_t)(2 * k) * HW]     = lo;
            outp1[(size_t)(2 * k + 1) * HW] = hi;
        }
    }
}

extern "C" void kernel_launch(void* const* d_in, const int* in_sizes, int n_in,
                              void* d_out, int out_size)
{
    const float* x = (const float*)d_in[0];   // [B, D, H, W]
    const float* w = (const float*)d_in[1];   // [B, 75, H, W]
    float* out = (float*)d_out;

    float* ybuf = nullptr;
    cudaGetSymbolAddress((void**)&ybuf, g_y);

    cudaFuncSetAttribute(lga_kernel,
                         cudaFuncAttributeMaxDynamicSharedMemorySize, SMEM_BYTES);

    dim3 grid(WW / TW, HH / TH, BB);   // 20 x 20 x 2
    lga_kernel<<<grid, NT, SMEM_BYTES>>>(x, w, ybuf);   // pass 1
    lga_kernel<<<grid, NT, SMEM_BYTES>>>(ybuf, w, out); // pass 2
}